// round 13
// baseline (speedup 1.0000x reference)
#include <cuda_runtime.h>
#include <cstdint>

#define N_UNITS   400
#define N_NEIGHB  64
#define N_CELLS   (N_UNITS * N_NEIGHB)   // 25600
#define BLK       256

// Scratch (no device allocation allowed). Layout: cell = nb * N_UNITS + u.
__device__ int   g_counts[N_CELLS];                 // phase1: cnt(c0); phase3 adds c1,c2 -> cnt_all
__device__ int   g_ex[N_CELLS];                     // explore counts, then final counts after fixup
__device__ short g_explore[N_NEIGHB * N_UNITS];     // sorted overlapping units per neighborhood
__device__ int   g_nexplore[N_NEIGHB];

// ---------------------------------------------------------------------------
// JAX threefry2x32-20, partitionable path, key = jax.random.key(1) -> (0, 1).
// (verified bit-exact: rel_err == 0.0 in rounds 11-12)
// ---------------------------------------------------------------------------
__device__ __forceinline__ float tf_uniform(unsigned i) {
    const unsigned k0 = 0u;
    const unsigned k1 = 1u;
    const unsigned k2 = 0x1BD11BDAu ^ k0 ^ k1;   // 0x1BD11BDB

    unsigned x0 = 0u + k0;
    unsigned x1 = i + k1;

#define TF_ROUND(r) { x0 += x1; x1 = __funnelshift_l(x1, x1, (r)); x1 ^= x0; }

    TF_ROUND(13) TF_ROUND(15) TF_ROUND(26) TF_ROUND(6)
    x0 += k1; x1 += k2 + 1u;
    TF_ROUND(17) TF_ROUND(29) TF_ROUND(16) TF_ROUND(24)
    x0 += k2; x1 += k0 + 2u;
    TF_ROUND(13) TF_ROUND(15) TF_ROUND(26) TF_ROUND(6)
    x0 += k0; x1 += k1 + 3u;
    TF_ROUND(17) TF_ROUND(29) TF_ROUND(16) TF_ROUND(24)
    x0 += k1; x1 += k2 + 4u;
    TF_ROUND(13) TF_ROUND(15) TF_ROUND(26) TF_ROUND(6)
    x0 += k2; x1 += k0 + 5u;

#undef TF_ROUND

    unsigned bits = x0 ^ x1;
    return __uint_as_float((bits >> 9) | 0x3f800000u) - 1.0f;
}

// ---------------------------------------------------------------------------
__global__ void zero_counts_kernel() {
    int i = blockIdx.x * blockDim.x + threadIdx.x;
    if (i < N_CELLS) { g_counts[i] = 0; g_ex[i] = 0; }
}

// 4 spikes per thread, vectorized loads.
__global__ void phase1_kernel(const int* __restrict__ top,
                              const int* __restrict__ nbid, int n) {
    int g = blockIdx.x * blockDim.x + threadIdx.x;   // group of 4 spikes
    int base = g * 4;
    if (base + 4 <= n) {
        const int4* t4 = (const int4*)(top + (size_t)base * 3);
        int4 a = t4[0], b = t4[1], c = t4[2];        // 12 ints = 4 spikes
        int4 nb = ((const int4*)nbid)[g];
        // top0 of spike k is element 3k: a.x, a.w, c.y... indices 0,3,6,9
        atomicAdd(&g_counts[nb.x * N_UNITS + a.x], 1);
        atomicAdd(&g_counts[nb.y * N_UNITS + a.w], 1);
        atomicAdd(&g_counts[nb.z * N_UNITS + b.z], 1);
        atomicAdd(&g_counts[nb.w * N_UNITS + c.y], 1);
    } else {
        for (int i = base; i < n; i++) {
            int u  = top[i * 3];
            int nb = nbid[i];
            atomicAdd(&g_counts[nb * N_UNITS + u], 1);
        }
    }
}

// One block per neighborhood; coalesced read of g_counts[nb*400 + u].
__global__ void build_explore_kernel() {
    __shared__ int warp_sums[13];
    int nb   = blockIdx.x;
    int u    = threadIdx.x;        // blockDim = 416 = 13 warps
    int lane = u & 31;
    int wid  = u >> 5;

    int flag = 0;
    if (u < N_UNITS) flag = (g_counts[nb * N_UNITS + u] > 0) ? 1 : 0;

    unsigned ballot = __ballot_sync(0xffffffffu, flag);
    int prefix = __popc(ballot & ((1u << lane) - 1u));
    if (lane == 0) warp_sums[wid] = __popc(ballot);
    __syncthreads();

    int base = 0;
#pragma unroll
    for (int w = 0; w < 13; w++)
        if (w < wid) base += warp_sums[w];

    if (flag) g_explore[nb * N_UNITS + base + prefix] = (short)u;

    if (u == 0) {
        int tot = 0;
#pragma unroll
        for (int w = 0; w < 13; w++) tot += warp_sums[w];
        g_nexplore[nb] = tot;
    }
}

// ---------------------------------------------------------------------------
// Main per-spike kernel. 3 atomics/spike; candidates staged once (float2 STS);
// scores computed inline during the coalesced flush from the staged cands.
// ---------------------------------------------------------------------------
__global__ __launch_bounds__(BLK)
void phase3_kernel(const float* __restrict__ logliks,
                   const int*   __restrict__ top,
                   const int*   __restrict__ usn,
                   const int*   __restrict__ nbid,
                   float*       __restrict__ out,
                   int n) {
    __shared__ int   s_usn[N_UNITS * 2];
    __shared__ float s_ll[N_UNITS];
    __shared__ int   s_ne[N_NEIGHB];
    __shared__ int   s_top[BLK * 3];
    __shared__ float s_cand[BLK * 10];

    const int t    = threadIdx.x;
    const int base = blockIdx.x * BLK;

    // vectorized preloads
    if (t < N_UNITS * 2 / 4) ((int4*)s_usn)[t] = ((const int4*)usn)[t];
    if (t < N_UNITS / 4)     ((float4*)s_ll)[t] = ((const float4*)logliks)[t];
    if (t >= BLK - N_NEIGHB) s_ne[t - (BLK - N_NEIGHB)] = g_nexplore[t - (BLK - N_NEIGHB)];

    const bool full = (base + BLK <= n);
    if (full) {
        if (t < 192) ((int4*)s_top)[t] = ((const int4*)(top + (size_t)base * 3))[t];
    } else {
        const int ntop = n * 3;
        for (int k = t; k < BLK * 3; k += BLK) {
            int g = base * 3 + k;
            s_top[k] = (g < ntop) ? top[g] : 0;
        }
    }
    __syncthreads();

    const int i = base + t;

    if (i < n) {
        int c[10];
        c[0] = s_top[t * 3 + 0];
        c[1] = s_top[t * 3 + 1];
        c[2] = s_top[t * 3 + 2];
        int nb = nbid[i];

        c[3] = s_usn[2 * c[0]];     c[4] = s_usn[2 * c[0] + 1];
        c[5] = s_usn[2 * c[1]];     c[6] = s_usn[2 * c[1] + 1];
        c[7] = s_usn[2 * c[2]];     c[8] = s_usn[2 * c[2] + 1];

        int ne = s_ne[nb];
        float u = tf_uniform((unsigned)i);
        if (ne > 0) {
            int targ = __float2int_rd(u * (float)ne);
            targ = min(targ, ne - 1);
            c[9] = (int)g_explore[nb * N_UNITS + targ];
        } else {
            c[9] = -1;
        }

        // counts: c1, c2 here; c0 done in phase1; search neighbors via fixup
        atomicAdd(&g_counts[nb * N_UNITS + c[1]], 1);
        atomicAdd(&g_counts[nb * N_UNITS + c[2]], 1);
        if (c[9] >= 0)
            atomicAdd(&g_ex[nb * N_UNITS + c[9]], 1);

        // in-place dedup (semantics-preserving, see round 12)
#pragma unroll
        for (int j = 1; j < 10; j++) {
            bool dup = false;
#pragma unroll
            for (int k = 0; k < 10; k++)
                if (k < j) dup |= (c[j] == c[k]);
            if (dup) c[j] = -1;
        }

        // stage candidates as float, 64-bit stores (t*10*4 bytes is 8B aligned)
#pragma unroll
        for (int j = 0; j < 10; j += 2) {
            float2 v;
            v.x = (float)c[j];
            v.y = (float)c[j + 1];
            *(float2*)&s_cand[t * 10 + j] = v;
        }
    }
    __syncthreads();

    // coalesced flush: read cand4 once, write cand4 + score4
    float* dstc = out + (size_t)base * 10;
    float* dsts = out + (size_t)n * 10 + (size_t)N_CELLS + (size_t)base * 10;

    if (full) {
        const int total4 = BLK * 10 / 4;   // 640
        const float4* s4 = (const float4*)s_cand;
        float4* dc4 = (float4*)dstc;
        float4* ds4 = (float4*)dsts;
        for (int k = t; k < total4; k += BLK) {
            float4 v = s4[k];
            dc4[k] = v;
            float4 s;
            s.x = (v.x >= 0.0f) ? s_ll[(int)v.x] : 0.0f;
            s.y = (v.y >= 0.0f) ? s_ll[(int)v.y] : 0.0f;
            s.z = (v.z >= 0.0f) ? s_ll[(int)v.z] : 0.0f;
            s.w = (v.w >= 0.0f) ? s_ll[(int)v.w] : 0.0f;
            ds4[k] = s;
        }
    } else {
        int rows  = n - base;
        int total = rows * 10;
        for (int k = t; k < total; k += BLK) {
            float v = s_cand[k];
            dstc[k] = v;
            dsts[k] = (v >= 0.0f) ? s_ll[(int)v] : 0.0f;
        }
    }
}

// Expand search-neighbor contributions into g_ex (which holds explore counts):
// final(u,nb) = cnt_ex + cnt_all(u,nb) + sum over v with usn[v,*]==u of cnt_all(v,nb)
__global__ void fixup_kernel(const int* __restrict__ usn) {
    int i = blockIdx.x * blockDim.x + threadIdx.x;
    if (i < N_CELLS) {
        int a = g_counts[i];
        if (a) {
            int nb = i / N_UNITS;
            int u  = i - nb * N_UNITS;
            atomicAdd(&g_ex[i], a);
            atomicAdd(&g_ex[nb * N_UNITS + usn[2 * u]], a);
            atomicAdd(&g_ex[nb * N_UNITS + usn[2 * u + 1]], a);
        }
    }
}

// out layout wants counts[u, nb]; scratch is [nb, u] -> transpose on write.
__global__ void counts_out_kernel(float* __restrict__ dst) {
    int j = blockIdx.x * blockDim.x + threadIdx.x;   // j = u*64 + nb
    if (j < N_CELLS) {
        int u  = j >> 6;
        int nb = j & 63;
        dst[j] = (float)g_ex[nb * N_UNITS + u];
    }
}

// ---------------------------------------------------------------------------
extern "C" void kernel_launch(void* const* d_in, const int* in_sizes, int n_in,
                              void* d_out, int out_size) {
    const float* logliks = (const float*)d_in[0];   // (400,) f32
    const int*   top     = (const int*)  d_in[1];   // (n, 3) i32
    const int*   usn     = (const int*)  d_in[2];   // (400, 2) i32
    const int*   nbid    = (const int*)  d_in[3];   // (n,) i32
    float*       out     = (float*)d_out;

    const int n = in_sizes[3];
    const int ngroups = (n + 3) / 4;

    zero_counts_kernel<<<(N_CELLS + BLK - 1) / BLK, BLK>>>();
    phase1_kernel<<<(ngroups + BLK - 1) / BLK, BLK>>>(top, nbid, n);
    build_explore_kernel<<<N_NEIGHB, 416>>>();
    phase3_kernel<<<(n + BLK - 1) / BLK, BLK>>>(logliks, top, usn, nbid, out, n);
    fixup_kernel<<<(N_CELLS + BLK - 1) / BLK, BLK>>>(usn);
    counts_out_kernel<<<(N_CELLS + BLK - 1) / BLK, BLK>>>(out + (size_t)n * 10);
}

// round 14
// speedup vs baseline: 1.0303x; 1.0303x over previous
#include <cuda_runtime.h>
#include <cstdint>

#define N_UNITS   400
#define N_NEIGHB  64
#define N_CELLS   (N_UNITS * N_NEIGHB)   // 25600
#define BLK       256
#define SPB       (2 * BLK)              // spikes per block in phase3
#define RCAP      32                     // reverse-neighbor capacity

// Scratch (no device allocation allowed). Layout: cell = nb * N_UNITS + u.
__device__ int   g_counts[N_CELLS];                 // cnt_all after phase3 (c0+c1+c2)
__device__ int   g_ex[N_CELLS];                     // explore counts
__device__ short g_explore[N_NEIGHB * N_UNITS];
__device__ int   g_nexplore[N_NEIGHB];
__device__ int   g_rdeg[N_UNITS];                   // reverse-neighbor degrees
__device__ int   g_rdat[N_UNITS * RCAP];            // reverse-neighbor lists

// ---------------------------------------------------------------------------
// JAX threefry2x32-20, partitionable path, key = jax.random.key(1) -> (0, 1).
// (verified bit-exact: rel_err == 0.0 in rounds 11-13)
// ---------------------------------------------------------------------------
__device__ __forceinline__ float tf_uniform(unsigned i) {
    const unsigned k0 = 0u;
    const unsigned k1 = 1u;
    const unsigned k2 = 0x1BD11BDAu ^ k0 ^ k1;

    unsigned x0 = 0u + k0;
    unsigned x1 = i + k1;

#define TF_ROUND(r) { x0 += x1; x1 = __funnelshift_l(x1, x1, (r)); x1 ^= x0; }

    TF_ROUND(13) TF_ROUND(15) TF_ROUND(26) TF_ROUND(6)
    x0 += k1; x1 += k2 + 1u;
    TF_ROUND(17) TF_ROUND(29) TF_ROUND(16) TF_ROUND(24)
    x0 += k2; x1 += k0 + 2u;
    TF_ROUND(13) TF_ROUND(15) TF_ROUND(26) TF_ROUND(6)
    x0 += k0; x1 += k1 + 3u;
    TF_ROUND(17) TF_ROUND(29) TF_ROUND(16) TF_ROUND(24)
    x0 += k1; x1 += k2 + 4u;
    TF_ROUND(13) TF_ROUND(15) TF_ROUND(26) TF_ROUND(6)
    x0 += k2; x1 += k0 + 5u;

#undef TF_ROUND

    unsigned bits = x0 ^ x1;
    return __uint_as_float((bits >> 9) | 0x3f800000u) - 1.0f;
}

// ---------------------------------------------------------------------------
__global__ void zero_counts_kernel() {
    int i = blockIdx.x * blockDim.x + threadIdx.x;
    if (i < N_CELLS) { g_counts[i] = 0; g_ex[i] = 0; }
    if (i < N_UNITS) g_rdeg[i] = 0;
}

// 4 spikes per thread, vectorized loads.
__global__ void phase1_kernel(const int* __restrict__ top,
                              const int* __restrict__ nbid, int n) {
    int g = blockIdx.x * blockDim.x + threadIdx.x;
    int base = g * 4;
    if (base + 4 <= n) {
        const int4* t4 = (const int4*)(top + (size_t)base * 3);
        int4 a = t4[0], b = t4[1], c = t4[2];
        int4 nb = ((const int4*)nbid)[g];
        atomicAdd(&g_counts[nb.x * N_UNITS + a.x], 1);
        atomicAdd(&g_counts[nb.y * N_UNITS + a.w], 1);
        atomicAdd(&g_counts[nb.z * N_UNITS + b.z], 1);
        atomicAdd(&g_counts[nb.w * N_UNITS + c.y], 1);
    } else {
        for (int i = base; i < n; i++) {
            int u  = top[i * 3];
            int nb = nbid[i];
            atomicAdd(&g_counts[nb * N_UNITS + u], 1);
        }
    }
}

// Build reverse-neighbor lists (after zero_counts; read by counts_out).
__global__ void revmap_kernel(const int* __restrict__ usn) {
    int v = blockIdx.x * blockDim.x + threadIdx.x;
    if (v < N_UNITS) {
        int u0 = usn[2 * v];
        int u1 = usn[2 * v + 1];
        int s0 = atomicAdd(&g_rdeg[u0], 1);
        g_rdat[u0 * RCAP + min(s0, RCAP - 1)] = v;
        int s1 = atomicAdd(&g_rdeg[u1], 1);
        g_rdat[u1 * RCAP + min(s1, RCAP - 1)] = v;
    }
}

// One block per neighborhood; coalesced read of g_counts[nb*400 + u].
__global__ void build_explore_kernel() {
    __shared__ int warp_sums[13];
    int nb   = blockIdx.x;
    int u    = threadIdx.x;        // blockDim = 416 = 13 warps
    int lane = u & 31;
    int wid  = u >> 5;

    int flag = 0;
    if (u < N_UNITS) flag = (g_counts[nb * N_UNITS + u] > 0) ? 1 : 0;

    unsigned ballot = __ballot_sync(0xffffffffu, flag);
    int prefix = __popc(ballot & ((1u << lane) - 1u));
    if (lane == 0) warp_sums[wid] = __popc(ballot);
    __syncthreads();

    int base = 0;
#pragma unroll
    for (int w = 0; w < 13; w++)
        if (w < wid) base += warp_sums[w];

    if (flag) g_explore[nb * N_UNITS + base + prefix] = (short)u;

    if (u == 0) {
        int tot = 0;
#pragma unroll
        for (int w = 0; w < 13; w++) tot += warp_sums[w];
        g_nexplore[nb] = tot;
    }
}

// ---------------------------------------------------------------------------
// Main kernel: 2 spikes per thread; both threefry chains issued back-to-back
// for 2-way ILP through the serial ALU dependency chain.
// ---------------------------------------------------------------------------
__global__ __launch_bounds__(BLK)
void phase3_kernel(const float* __restrict__ logliks,
                   const int*   __restrict__ top,
                   const int*   __restrict__ usn,
                   const int*   __restrict__ nbid,
                   float*       __restrict__ out,
                   int n) {
    __shared__ int2  s_usn[N_UNITS];
    __shared__ float s_ll[N_UNITS];
    __shared__ int   s_ne[N_NEIGHB];
    __shared__ int   s_top[SPB * 3];
    __shared__ float s_cand[BLK * 10];

    const int t    = threadIdx.x;
    const int base = blockIdx.x * SPB;

    if (t < N_UNITS / 2)   ((int4*)s_usn)[t] = ((const int4*)usn)[t];
    if (t < N_UNITS / 4)   ((float4*)s_ll)[t] = ((const float4*)logliks)[t];
    if (t >= BLK - N_NEIGHB) s_ne[t - (BLK - N_NEIGHB)] = g_nexplore[t - (BLK - N_NEIGHB)];

    const bool full = (base + SPB <= n);
    if (full) {
        // 512*3 = 1536 ints = 384 int4
        const int4* src = (const int4*)(top + (size_t)base * 3);
        ((int4*)s_top)[t] = src[t];
        if (t < 128) ((int4*)s_top)[t + BLK] = src[t + BLK];
    } else {
        const int ntop = n * 3;
        for (int k = t; k < SPB * 3; k += BLK) {
            int g = base * 3 + k;
            s_top[k] = (g < ntop) ? top[g] : 0;
        }
    }
    __syncthreads();

    const int i0 = base + t;
    const int i1 = base + BLK + t;
    const bool a0 = (i0 < n);
    const bool a1 = (i1 < n);

    // Both threefry chains up front (independent -> 2-way ILP)
    float u0 = tf_uniform((unsigned)i0);
    float u1 = tf_uniform((unsigned)i1);

    int nb0 = 0, nb1 = 0;
    if (a0) nb0 = nbid[i0];
    if (a1) nb1 = nbid[i1];

    int c9_0 = -1, c9_1 = -1;
    if (a0) {
        int ne = s_ne[nb0];
        if (ne > 0) {
            int targ = min(__float2int_rd(u0 * (float)ne), ne - 1);
            c9_0 = (int)g_explore[nb0 * N_UNITS + targ];
        }
    }
    if (a1) {
        int ne = s_ne[nb1];
        if (ne > 0) {
            int targ = min(__float2int_rd(u1 * (float)ne), ne - 1);
            c9_1 = (int)g_explore[nb1 * N_UNITS + targ];
        }
    }

#define PROCESS_SPIKE(ACT, TOFF, NB, C9)                                     \
    if (ACT) {                                                               \
        int c[10];                                                           \
        c[0] = s_top[(TOFF) * 3 + 0];                                        \
        c[1] = s_top[(TOFF) * 3 + 1];                                        \
        c[2] = s_top[(TOFF) * 3 + 2];                                        \
        int2 p0 = s_usn[c[0]];  c[3] = p0.x;  c[4] = p0.y;                   \
        int2 p1 = s_usn[c[1]];  c[5] = p1.x;  c[6] = p1.y;                   \
        int2 p2 = s_usn[c[2]];  c[7] = p2.x;  c[8] = p2.y;                   \
        c[9] = (C9);                                                         \
        atomicAdd(&g_counts[(NB) * N_UNITS + c[1]], 1);                      \
        atomicAdd(&g_counts[(NB) * N_UNITS + c[2]], 1);                      \
        if (c[9] >= 0) atomicAdd(&g_ex[(NB) * N_UNITS + c[9]], 1);           \
        _Pragma("unroll")                                                    \
        for (int j = 1; j < 10; j++) {                                       \
            bool dup = false;                                                \
            _Pragma("unroll")                                                \
            for (int k = 0; k < 10; k++)                                     \
                if (k < j) dup |= (c[j] == c[k]);                            \
            if (dup) c[j] = -1;                                              \
        }                                                                    \
        _Pragma("unroll")                                                    \
        for (int j = 0; j < 10; j += 2) {                                    \
            float2 v; v.x = (float)c[j]; v.y = (float)c[j + 1];              \
            *(float2*)&s_cand[t * 10 + j] = v;                               \
        }                                                                    \
    }

#define FLUSH_HALF(H)                                                        \
    {                                                                        \
        const int hb = base + (H) * BLK;                                     \
        float* dstc = out + (size_t)hb * 10;                                 \
        float* dsts = out + (size_t)n * 10 + (size_t)N_CELLS + (size_t)hb * 10; \
        if (hb + BLK <= n) {                                                 \
            const float4* s4 = (const float4*)s_cand;                       \
            float4* dc4 = (float4*)dstc;                                     \
            float4* ds4 = (float4*)dsts;                                     \
            _Pragma("unroll")                                                \
            for (int m = 0; m < 3; m++) {                                    \
                int k = t + m * BLK;                                         \
                if (m < 2 || k < BLK * 10 / 4) {                             \
                    float4 v = s4[k];                                        \
                    __stcs(&dc4[k], v);                                      \
                    float4 s;                                                \
                    s.x = (v.x >= 0.0f) ? s_ll[(int)v.x] : 0.0f;             \
                    s.y = (v.y >= 0.0f) ? s_ll[(int)v.y] : 0.0f;             \
                    s.z = (v.z >= 0.0f) ? s_ll[(int)v.z] : 0.0f;             \
                    s.w = (v.w >= 0.0f) ? s_ll[(int)v.w] : 0.0f;             \
                    __stcs(&ds4[k], s);                                      \
                }                                                            \
            }                                                                \
        } else if (hb < n) {                                                 \
            int total = (n - hb) * 10;                                       \
            for (int k = t; k < total; k += BLK) {                           \
                float v = s_cand[k];                                         \
                dstc[k] = v;                                                 \
                dsts[k] = (v >= 0.0f) ? s_ll[(int)v] : 0.0f;                 \
            }                                                                \
        }                                                                    \
    }

    PROCESS_SPIKE(a0, t, nb0, c9_0)
    __syncthreads();
    FLUSH_HALF(0)
    __syncthreads();
    PROCESS_SPIKE(a1, BLK + t, nb1, c9_1)
    __syncthreads();
    FLUSH_HALF(1)

#undef PROCESS_SPIKE
#undef FLUSH_HALF
}

// final(u,nb) = explore + cnt_all(u,nb) + sum_{v in R(u)} cnt_all(v,nb)
// (v appears twice in R(u) if both its search neighbors are u — matches ref)
__global__ void counts_out_kernel(float* __restrict__ dst) {
    int j = blockIdx.x * blockDim.x + threadIdx.x;   // j = u*64 + nb
    if (j < N_CELLS) {
        int u  = j >> 6;
        int nb = j & 63;
        int acc = g_ex[nb * N_UNITS + u] + g_counts[nb * N_UNITS + u];
        int deg = g_rdeg[u];                          // warp-uniform
        for (int d = 0; d < deg; d++) {
            int v = g_rdat[u * RCAP + d];             // warp-uniform broadcast
            acc += g_counts[nb * N_UNITS + v];
        }
        dst[j] = (float)acc;
    }
}

// ---------------------------------------------------------------------------
extern "C" void kernel_launch(void* const* d_in, const int* in_sizes, int n_in,
                              void* d_out, int out_size) {
    const float* logliks = (const float*)d_in[0];   // (400,) f32
    const int*   top     = (const int*)  d_in[1];   // (n, 3) i32
    const int*   usn     = (const int*)  d_in[2];   // (400, 2) i32
    const int*   nbid    = (const int*)  d_in[3];   // (n,) i32
    float*       out     = (float*)d_out;

    const int n = in_sizes[3];
    const int ngroups = (n + 3) / 4;

    zero_counts_kernel<<<(N_CELLS + BLK - 1) / BLK, BLK>>>();
    phase1_kernel<<<(ngroups + BLK - 1) / BLK, BLK>>>(top, nbid, n);
    revmap_kernel<<<2, 200>>>(usn);
    build_explore_kernel<<<N_NEIGHB, 416>>>();
    phase3_kernel<<<(n + SPB - 1) / SPB, BLK>>>(logliks, top, usn, nbid, out, n);
    counts_out_kernel<<<(N_CELLS + BLK - 1) / BLK, BLK>>>(out + (size_t)n * 10);
}